// round 4
// baseline (speedup 1.0000x reference)
#include <cuda_runtime.h>
#include <cstdint>

typedef unsigned int u32;
typedef unsigned long long u64;

#define NT 512
#define SLEN 65544
#define NEMB 65536

// ---------------- scratch (device globals; no allocation) ----------------
__device__ __align__(16) u32 g_exp[(NEMB * 256) / 4];  // decoded exponent bytes
__device__ uint2 g_lut[4096];                          // {freq, bias = slot - cum}
__device__ u32 g_symtab[4096];

// ---------------- build fused per-slot LUT ----------------
__global__ void k_build_lut(const int* __restrict__ tables,
                            const int* __restrict__ slot_map) {
    int s = blockIdx.x * blockDim.x + threadIdx.x;
    if (s < 4096) {
        u32 sym = (u32)slot_map[s];
        u32 t = (u32)tables[sym];
        u32 freq = t >> 16;
        u32 cum = t & 0xFFFFu;
        g_lut[s] = make_uint2(freq, (u32)s - cum);
        g_symtab[s] = sym;
    }
}

// pack 4 raw int32 "bytes" big-endian-first into one u32 (first byte at MSB)
__device__ __forceinline__ u32 pack_be(int4 v) {
    u32 t1 = __byte_perm((u32)v.z, (u32)v.w, 0x0004); // b0=w0, b1=z0
    u32 t2 = __byte_perm((u32)v.x, (u32)v.y, 0x0004); // b0=y0, b1=x0
    return __byte_perm(t1, t2, 0x5410);               // [x0 y0 z0 w0]
}

// ---------------- the serial rANS decode ----------------
// 128 blocks x 4 warps; warp w decodes tile bid*4+w on its own SMSP.
// Lane 0 runs the chain; all 128 threads stage the LUT.
__global__ void __launch_bounds__(128, 1)
k_decode(const int* __restrict__ stream,
         const int* __restrict__ tile_offsets,
         const int* __restrict__ states) {
    __shared__ uint2 LUT[4096];
    __shared__ unsigned char SYMT[4096];
    int tid = threadIdx.x;
#pragma unroll 4
    for (int i = tid; i < 4096; i += 128) {
        LUT[i] = g_lut[i];
        SYMT[i] = (unsigned char)g_symtab[i];
    }
    __syncthreads();
    if ((tid & 31) != 0) return;

    int tile = blockIdx.x * 4 + (tid >> 5);
    u32 state = (u32)states[tile];
    const int4* sp = (const int4*)(stream + tile_offsets[tile]);

    // 8-byte static window (MSB = next stream byte) + pos = bytes consumed,
    // refilled 4 bytes at a time from a 2-deep prefetch pipeline.
    u64 w64 = ((u64)pack_be(__ldg(sp + 0)) << 32) | (u64)pack_be(__ldg(sp + 1));
    u32 nb = pack_be(__ldg(sp + 2));
    int4 pf = __ldg(sp + 3);
    int idx = 4;      // int4 units (4 stream bytes each)
    int pos = 0;      // bytes consumed from w64 (invariant: <=3 at group start)

    int rt = tile >> 3, ct = tile & 7;
    uint4* outp = (uint4*)g_exp;
    u32 ob = (u32)rt * 16384u + (u32)ct * 2u;  // uint4 index for (k=0, half=0)

    for (int i = 0; i < 2048; ++i) {           // 16 symbols per iteration
        u32 wacc[4];
#pragma unroll
        for (int j = 0; j < 4; ++j) {          // one output u32 word = 4 symbols
            u32 accw = 0;
#pragma unroll
            for (int g = 0; g < 2; ++g) {      // group of 2 symbols + refill
#pragma unroll
                for (int s = 0; s < 2; ++s) {
                    u32 slot = state & 4095u;
                    uint2 e = LUT[slot];                 // on-chain LDS.64
                    u32 sym = (u32)SYMT[slot];           // off-chain
                    u32 sh = 48u - 8u * (u32)pos;
                    u32 b01 = (u32)(w64 >> sh);          // bytes[pos],[pos+1] in low 16
                    u32 d = e.x * (state >> 12) + e.y;   // freq*(state>>12)+bias
                    bool p1 = d < (1u << 23);
                    bool p2 = d < (1u << 15);            // implies p1
                    u32 c1 = (d << 8) | ((b01 >> 8) & 0xFFu);
                    u32 c2 = (d << 16) | (b01 & 0xFFFFu);
                    u32 ns = p1 ? c1 : d;
                    state = p2 ? c2 : ns;
                    pos += (int)p1 + (int)p2;
                    accw |= sym << (8 * (2 * g + s));
                }
                // refill: splice 4 bytes when >=4 consumed (restores pos<=3)
                bool need = pos >= 4;
                u64 wref = (w64 << 32) | (u64)nb;
                w64 = need ? wref : w64;
                pos = need ? pos - 4 : pos;
                if (need) {
                    nb = pack_be(pf);
                    int ci = idx < 16385 ? idx : 16385;  // clamp: never read OOB
                    pf = __ldg(sp + ci);
                    idx++;
                }
            }
            wacc[j] = accw;
        }
        outp[ob] = make_uint4(wacc[0], wacc[1], wacc[2], wacc[3]);
        ob += (i & 1) ? 15u : 1u;              // half0->half1: +1; then next k: +15
    }
}

// ---------------- gather: out[l, :] = f32(bf16(exp<<8 | man)) of row x[l] ----------------
__global__ void __launch_bounds__(256)
k_gather(const int* __restrict__ x, const int4* __restrict__ man,
         float4* __restrict__ out) {
    int l = blockIdx.x * 4 + (threadIdx.x >> 6);
    int c = threadIdx.x & 63;
    int row = x[l];
    u32 e = g_exp[row * 64 + c];
    int4 m = __ldg(man + row * 64 + c);  // raw int32 mantissa bytes
    float4 o;
    o.x = __uint_as_float(((e & 0xFFu) << 24) | (((u32)m.x & 0xFFu) << 16));
    o.y = __uint_as_float((((e >> 8) & 0xFFu) << 24) | (((u32)m.y & 0xFFu) << 16));
    o.z = __uint_as_float((((e >> 16) & 0xFFu) << 24) | (((u32)m.z & 0xFFu) << 16));
    o.w = __uint_as_float((e & 0xFF000000u) | (((u32)m.w & 0xFFu) << 16));
    out[(size_t)l * 64 + (size_t)c] = o;
}

// ---------------- launch ----------------
extern "C" void kernel_launch(void* const* d_in, const int* in_sizes, int n_in,
                              void* d_out, int out_size) {
    const int* x       = (const int*)d_in[0];
    const int* stream  = (const int*)d_in[1];
    const int* states  = (const int*)d_in[2];
    const int* tables  = (const int*)d_in[3];
    const int* slotmap = (const int*)d_in[4];
    const int* toffs   = (const int*)d_in[5];
    // d_in[6] = tile_max_lens (uniform; unused)
    const int* manraw  = (const int*)d_in[7];
    float* out = (float*)d_out;

    k_build_lut<<<16, 256>>>(tables, slotmap);
    k_decode<<<128, 128>>>(stream, toffs, states);
    k_gather<<<65536, 256>>>(x, (const int4*)manraw, (float4*)out);
}